// round 17
// baseline (speedup 1.0000x reference)
#include <cuda_runtime.h>
#include <cuda_fp16.h>
#include <cstdint>

#define DEVI static __device__ __forceinline__

namespace {
constexpr int B_ = 256;   // batch
constexpr int T_ = 256;   // time
constexpr int D_ = 64;    // input dim
constexpr int H_ = 512;   // hidden
constexpr int FOURH = 4 * H_;          // 2048
constexpr int M_ALL = B_ * T_;         // 65536

// step-kernel tiling: 4 batch-groups x 64 rows, 32 j-tiles x 16 cols
constexpr int MB = 64;                 // batch rows per block
constexpr int WJ = 16;                 // hidden cols per block (per gate)
constexpr int GRID_S = 128;            // 4 * 32
constexpr int THR_S = 512;             // 16 warps: gate (4) x batch-quarter (4)

constexpr int G_STRIDE = 17;

// step-kernel dynamic smem:
//   W: FULL tile, 64 rows (4 gates x 16 cols) x 512 fp16 = 256 words + 4 pad
//   A: 4 stages of K=128 chunks (64 words + 4 pad per row), no stage reuse
constexpr int W_ROW_W = 260;                            // words per W row
constexpr int W_WORDS = 64 * W_ROW_W;                   // 16640
constexpr int A_ROW_W = 68;                             // 64 data + 4 pad words
constexpr int A_ST_WORDS = 64 * A_ROW_W;                // 4352 per stage
constexpr int SW_OFF = 0;
constexpr int SA_OFF = W_WORDS;                         // 16640
constexpr int STEP_SMEM_WORDS = SA_OFF + 4 * A_ST_WORDS; // 34048
constexpr int STEP_SMEM_BYTES = STEP_SMEM_WORDS * 4;     // 136192 B
constexpr int NCHUNK = 4;              // 4 chunks of K=128 cover H=512
}

// ---------- scratch (device globals; NO allocations anywhere) ----------
__device__ float g_xw[(size_t)M_ALL * FOURH];  // input projections, layout [t][B][4H]
__device__ float g_h1[(size_t)M_ALL * H_];     // layer-0 hidden sequence [b][t][H] (fp32)
__device__ __half g_hbf[2][B_ * H_];           // fp16 ping-pong hidden state
__device__ __half g_whf[FOURH * H_];           // fp16 recurrent weights (current layer)
__device__ float g_c[B_ * H_];                 // cell state
__device__ float g_sum[B_ * H_];               // sum over t of layer-1 h
__device__ float g_head[B_ * 256];             // shared-head output

// ---------- helpers ----------
DEVI float tf32r(float x) {
    unsigned u;
    asm("cvt.rna.tf32.f32 %0, %1;" : "=r"(u) : "f"(x));
    return __uint_as_float(u);
}

DEVI void mma8(float* c, const unsigned* a, unsigned b0, unsigned b1) {
    asm volatile(
        "mma.sync.aligned.m16n8k8.row.col.f32.tf32.tf32.f32 "
        "{%0,%1,%2,%3}, {%4,%5,%6,%7}, {%8,%9}, {%0,%1,%2,%3};\n"
        : "+f"(c[0]), "+f"(c[1]), "+f"(c[2]), "+f"(c[3])
        : "r"(a[0]), "r"(a[1]), "r"(a[2]), "r"(a[3]), "r"(b0), "r"(b1));
}

DEVI void mma16(float* c, const unsigned* a, unsigned b0, unsigned b1) {
    asm volatile(
        "mma.sync.aligned.m16n8k16.row.col.f32.f16.f16.f32 "
        "{%0,%1,%2,%3}, {%4,%5,%6,%7}, {%8,%9}, {%0,%1,%2,%3};\n"
        : "+f"(c[0]), "+f"(c[1]), "+f"(c[2]), "+f"(c[3])
        : "r"(a[0]), "r"(a[1]), "r"(a[2]), "r"(a[3]), "r"(b0), "r"(b1));
}

DEVI void cpasync16(void* dst_smem, const void* src) {
    unsigned d = (unsigned)__cvta_generic_to_shared(dst_smem);
    asm volatile("cp.async.cg.shared.global [%0], [%1], 16;\n" :: "r"(d), "l"(src));
}
DEVI void cpcommit() { asm volatile("cp.async.commit_group;\n" ::: "memory"); }
DEVI void cpwait2() { asm volatile("cp.async.wait_group 2;\n" ::: "memory"); }
DEVI void cpwait0() { asm volatile("cp.async.wait_group 0;\n" ::: "memory"); }

DEVI float sigmoidf_(float x) { return 1.0f / (1.0f + __expf(-x)); }

DEVI float tanhf_(float x) {
    x = fminf(fmaxf(x, -15.0f), 15.0f);
    float e = __expf(-2.0f * x);
    return (1.0f - e) / (1.0f + e);
}

// ---------- zero state ----------
__global__ void zero_state_kernel() {
    int i = blockIdx.x * blockDim.x + threadIdx.x;
    if (i < B_ * H_) {
        g_hbf[0][i] = __float2half(0.0f);
        g_c[i] = 0.0f;
        g_sum[i] = 0.0f;
    }
}

// ---------- fp32 -> fp16 weight conversion (one per layer; [4H][H] layout kept) ----------
__global__ void __launch_bounds__(256) conv_w_kernel(const float* __restrict__ W) {
    int i = blockIdx.x * blockDim.x + threadIdx.x;   // over FOURH*H/4 float4s
    if (i < FOURH * H_ / 4) {
        float4 v = *reinterpret_cast<const float4*>(W + (size_t)i * 4);
        __half2 h01 = __floats2half2_rn(v.x, v.y);
        __half2 h23 = __floats2half2_rn(v.z, v.w);
        uint2 u;
        u.x = *reinterpret_cast<unsigned*>(&h01);
        u.y = *reinterpret_cast<unsigned*>(&h23);
        *reinterpret_cast<uint2*>(&g_whf[(size_t)i * 4]) = u;
    }
}

// ---------- big input-projection GEMM (tf32, unchanged) ----------
// out[t][B][4H] = A[M][K] @ W[4H][K]^T + bias  (A rows m = b*T+t)
__global__ void __launch_bounds__(256) gemm_xw_kernel(
    const float* __restrict__ Aext, int useH1,
    const float* __restrict__ W, const float* __restrict__ bias, int K)
{
    __shared__ float As[128][36];
    __shared__ float Bs[64][36];
    const float* __restrict__ A = useH1 ? g_h1 : Aext;

    const int tid = threadIdx.x;
    const int lane = tid & 31;
    const int w = tid >> 5;
    const int wm = w >> 1, wn = w & 1;
    const int grp = lane >> 2, tig = lane & 3;
    const int m0 = blockIdx.x * 128;
    const int j0 = blockIdx.y * 64;

    float acc[2][4][4] = {};

    for (int kc = 0; kc < K; kc += 32) {
        __syncthreads();
#pragma unroll
        for (int i = 0; i < 4; i++) {               // A tile 128x32
            int q = tid + 256 * i;
            int r = q >> 3, c4 = (q & 7) << 2;
            float4 v = *reinterpret_cast<const float4*>(&A[(size_t)(m0 + r) * K + kc + c4]);
            As[r][c4 + 0] = tf32r(v.x);
            As[r][c4 + 1] = tf32r(v.y);
            As[r][c4 + 2] = tf32r(v.z);
            As[r][c4 + 3] = tf32r(v.w);
        }
#pragma unroll
        for (int i = 0; i < 2; i++) {               // W tile 64x32
            int q = tid + 256 * i;
            int r = q >> 3, c4 = (q & 7) << 2;
            float4 v = *reinterpret_cast<const float4*>(&W[(size_t)(j0 + r) * K + kc + c4]);
            Bs[r][c4 + 0] = tf32r(v.x);
            Bs[r][c4 + 1] = tf32r(v.y);
            Bs[r][c4 + 2] = tf32r(v.z);
            Bs[r][c4 + 3] = tf32r(v.w);
        }
        __syncthreads();

#pragma unroll
        for (int ks = 0; ks < 4; ks++) {
            unsigned a[2][4];
#pragma unroll
            for (int mt = 0; mt < 2; mt++) {
                int rb = wm * 32 + mt * 16;
                a[mt][0] = __float_as_uint(As[rb + grp][ks * 8 + tig]);
                a[mt][1] = __float_as_uint(As[rb + grp + 8][ks * 8 + tig]);
                a[mt][2] = __float_as_uint(As[rb + grp][ks * 8 + tig + 4]);
                a[mt][3] = __float_as_uint(As[rb + grp + 8][ks * 8 + tig + 4]);
            }
#pragma unroll
            for (int nt = 0; nt < 4; nt++) {
                int cb = wn * 32 + nt * 8;
                unsigned b0 = __float_as_uint(Bs[cb + grp][ks * 8 + tig]);
                unsigned b1 = __float_as_uint(Bs[cb + grp][ks * 8 + tig + 4]);
                mma8(acc[0][nt], a[0], b0, b1);
                mma8(acc[1][nt], a[1], b0, b1);
            }
        }
    }

    // epilogue: + bias, permuted write to [t][B][4H]
#pragma unroll
    for (int mt = 0; mt < 2; mt++) {
#pragma unroll
        for (int nt = 0; nt < 4; nt++) {
            int row = m0 + wm * 32 + mt * 16 + grp;
            int col = j0 + wn * 32 + nt * 8 + tig * 2;
            float bv0 = bias[col], bv1 = bias[col + 1];
#pragma unroll
            for (int half = 0; half < 2; half++) {
                int r = row + half * 8;
                int t = r & (T_ - 1), b = r >> 8;
                size_t o = ((size_t)t * B_ + b) * FOURH + col;
                g_xw[o] = acc[mt][nt][half * 2 + 0] + bv0;
                g_xw[o + 1] = acc[mt][nt][half * 2 + 1] + bv1;
            }
        }
    }
}

// ---------- one LSTM timestep (fp16, full-W smem, 4 x K=128 A chunks) ----------
// Grid 128 blocks: bg = bid>>5 (64 batch rows), jt = bid&31 (16 hidden cols, all 4 gates).
// 512 threads / 16 warps: warp w -> gate (w&3), batch-quarter (w>>2, 16 rows).
// Plain launches only (no PDL / clusters / spins — those kill this bench).
// Full 64 KB W tile loads once in the prologue (same cp.async group as A chunk 0);
// mainloop has only 4 wait+barrier rounds over K=128 A chunks (4 stages, no reuse).
__global__ void __launch_bounds__(THR_S) lstm_step_kernel(
    int t, int mode)  // mode 0: write g_h1; 1: accumulate sum
{
    extern __shared__ __align__(16) unsigned smu[];
    unsigned* const SW = smu + SW_OFF;   // [64][260] words: full W tile (row = g*16+n)
    unsigned* const SA = smu + SA_OFF;   // [4][64][68] words: A stages

    const int tid = threadIdx.x;
    const int lane = tid & 31;
    const int w = tid >> 5;
    const int grp = lane >> 2, tig = lane & 3;
    const int bg = blockIdx.x >> 5;
    const int jt = blockIdx.x & 31;
    const int m0 = bg * MB;
    const int j0 = jt * WJ;
    const int g = w & 3;
    const int mb = (w >> 2) * 16;        // batch-quarter base row

    const __half* __restrict__ hprev = g_hbf[t & 1];
    __half* __restrict__ hnext = g_hbf[(t + 1) & 1];

    // epilogue operands up front (independent loads, hidden behind mainloop)
    const int b_loc = tid >> 3;          // 0..63
    const int hc0 = (tid & 7) * 2;       // 0..14
    const int b = m0 + b_loc;
    const size_t xo = ((size_t)t * B_ + b) * FOURH + j0 + hc0;
    const float2 xi  = __ldg(reinterpret_cast<const float2*>(&g_xw[xo]));
    const float2 xf  = __ldg(reinterpret_cast<const float2*>(&g_xw[xo + H_]));
    const float2 xg  = __ldg(reinterpret_cast<const float2*>(&g_xw[xo + 2 * H_]));
    const float2 xo2 = __ldg(reinterpret_cast<const float2*>(&g_xw[xo + 3 * H_]));
    const float2 c2  = *reinterpret_cast<const float2*>(&g_c[b * H_ + j0 + hc0]);

    // one A chunk (K=128): 1024 cp.async, 2/thread
    auto load_a = [&](int s, int kc) {
#pragma unroll
        for (int i = 0; i < 2; i++) {
            int p = tid + THR_S * i;
            int row = p >> 4, seg = p & 15;      // 16 x 16B segments per row
            cpasync16(&SA[(s * 64 + row) * A_ROW_W + seg * 4],
                      &hprev[(m0 + row) * H_ + kc + seg * 8]);
        }
    };

    // ---- prologue ----
    // group 0: FULL W tile (4096 cp.async, 8/thread) + A chunk 0
#pragma unroll
    for (int i = 0; i < 8; i++) {
        int idx = tid + THR_S * i;       // 0..4095
        int row = idx >> 6;              // 0..63 = g2*16+n
        int s16 = idx & 63;              // 16B segment (8 fp16)
        int g2 = row >> 4, n = row & 15;
        cpasync16(&SW[row * W_ROW_W + s16 * 4],
                  &g_whf[(size_t)(g2 * H_ + j0 + n) * H_ + s16 * 8]);
    }
    load_a(0, 0);    cpcommit();         // g0 = W + A0
    load_a(1, 128);  cpcommit();         // g1 = A1
    load_a(2, 256);  cpcommit();         // g2 = A2

    float acc[2][4] = {};

    for (int ci = 0; ci < NCHUNK; ci++) {
        cpwait2();              // all but 2 newest groups done -> W + A chunk ci resident
        __syncthreads();        // make the loaded stage visible block-wide
        if (ci + 3 < NCHUNK) load_a(ci + 3, (ci + 3) * 128);
        cpcommit();             // one commit per round keeps wait arithmetic uniform

        const unsigned* Ab = &SA[ci * A_ST_WORDS];
        const unsigned* Wb = &SW[(g * WJ) * W_ROW_W + ci * 64];
#pragma unroll
        for (int ks = 0; ks < 8; ks++) {            // 8 ksteps of k16 per 128-elem chunk
            unsigned a[4];
            a[0] = Ab[(mb + grp) * A_ROW_W + ks * 8 + tig];
            a[1] = Ab[(mb + grp + 8) * A_ROW_W + ks * 8 + tig];
            a[2] = Ab[(mb + grp) * A_ROW_W + ks * 8 + tig + 4];
            a[3] = Ab[(mb + grp + 8) * A_ROW_W + ks * 8 + tig + 4];
#pragma unroll
            for (int nt = 0; nt < 2; nt++) {
                unsigned b0 = Wb[(nt * 8 + grp) * W_ROW_W + ks * 8 + tig];
                unsigned b1 = Wb[(nt * 8 + grp) * W_ROW_W + ks * 8 + tig + 4];
                mma16(acc[nt], a, b0, b1);
            }
        }
    }
    cpwait0();   // drain empty tail groups

    // gate exchange: G (fp32, 4352 words) aliases A stage 0 exactly.
    // Stage 0 was only read at ci=0; every warp has passed the ci>=1 barriers.
    float* const Gsm = reinterpret_cast<float*>(&SA[0]);
#pragma unroll
    for (int nt = 0; nt < 2; nt++) {
        int r0 = mb + grp;
        int c = nt * 8 + tig * 2;
        Gsm[(g * MB + r0) * G_STRIDE + c]     = acc[nt][0];
        Gsm[(g * MB + r0) * G_STRIDE + c + 1] = acc[nt][1];
        Gsm[(g * MB + r0 + 8) * G_STRIDE + c]     = acc[nt][2];
        Gsm[(g * MB + r0 + 8) * G_STRIDE + c + 1] = acc[nt][3];
    }
    __syncthreads();

    // fused activation + cell update: 2 cells per thread
    float gi[2] = {xi.x, xi.y};
    float gf[2] = {xf.x, xf.y};
    float gg[2] = {xg.x, xg.y};
    float go[2] = {xo2.x, xo2.y};
    float cr[2] = {c2.x, c2.y};
    float hv[2];
#pragma unroll
    for (int j = 0; j < 2; j++) {
        int gb = b_loc * G_STRIDE + hc0 + j;
        float ii = sigmoidf_(Gsm[gb] + gi[j]);
        float ff = sigmoidf_(Gsm[MB * G_STRIDE + gb] + gf[j]);
        float gt = tanhf_(Gsm[2 * MB * G_STRIDE + gb] + gg[j]);
        float oo = sigmoidf_(Gsm[3 * MB * G_STRIDE + gb] + go[j]);
        cr[j] = ff * cr[j] + ii * gt;
        hv[j] = oo * tanhf_(cr[j]);
    }
    *reinterpret_cast<float2*>(&g_c[b * H_ + j0 + hc0]) = make_float2(cr[0], cr[1]);

    // fp16 h for the next step's A operand
    __half2 h01 = __floats2half2_rn(hv[0], hv[1]);
    *reinterpret_cast<unsigned*>(&hnext[b * H_ + j0 + hc0]) =
        *reinterpret_cast<unsigned*>(&h01);

    if (mode == 0) {
        *reinterpret_cast<float2*>(&g_h1[((size_t)b * T_ + t) * H_ + j0 + hc0]) =
            make_float2(hv[0], hv[1]);
    } else {
        float2 s2 = *reinterpret_cast<float2*>(&g_sum[b * H_ + j0 + hc0]);
        s2.x += hv[0]; s2.y += hv[1];
        *reinterpret_cast<float2*>(&g_sum[b * H_ + j0 + hc0]) = s2;
    }
}

// ---------- heads ----------
__global__ void __launch_bounds__(256) head1_kernel(
    const float* __restrict__ Wsh, const float* __restrict__ bsh)
{
    __shared__ float last[H_];
    const int b = blockIdx.x, j = threadIdx.x;
    for (int k = j; k < H_; k += 256) last[k] = g_sum[b * H_ + k] * (1.0f / (float)T_);
    __syncthreads();
    const float4* wr = reinterpret_cast<const float4*>(Wsh + (size_t)j * H_);
    const float4* lr = reinterpret_cast<const float4*>(last);
    float s = bsh[j];
#pragma unroll 4
    for (int k = 0; k < H_ / 4; k++) {
        float4 wv = wr[k], lv = lr[k];
        s += wv.x * lv.x + wv.y * lv.y + wv.z * lv.z + wv.w * lv.w;
    }
    g_head[b * 256 + j] = fmaxf(s, 0.0f) * 1.5f;
}

__global__ void __launch_bounds__(256) head2_kernel(
    const float* __restrict__ Wd, const float* __restrict__ bd,
    const float* __restrict__ Wm, const float* __restrict__ bm,
    float* __restrict__ out)
{
    const int b = threadIdx.x;
    const float4* hr = reinterpret_cast<const float4*>(g_head + b * 256);
    const float4* wd4 = reinterpret_cast<const float4*>(Wd);
    const float4* wm4 = reinterpret_cast<const float4*>(Wm);
    float sd = 0.0f, smv = 0.0f;
#pragma unroll 8
    for (int k = 0; k < 64; k++) {
        float4 h = hr[k], a = wd4[k], m = wm4[k];
        sd += h.x * a.x + h.y * a.y + h.z * a.z + h.w * a.w;
        smv += h.x * m.x + h.y * m.y + h.z * m.z + h.w * m.w;
    }
    out[b] = sd + bd[0];
    out[256 + b] = smv + bm[0];
}

// ---------- launch ----------
extern "C" void kernel_launch(void* const* d_in, const int* in_sizes, int n_in,
                              void* d_out, int out_size)
{
    (void)in_sizes; (void)n_in; (void)out_size;
    const float* x    = (const float*)d_in[0];
    const float* Wih0 = (const float*)d_in[1];
    const float* Whh0 = (const float*)d_in[2];
    const float* b0   = (const float*)d_in[3];
    const float* Wih1 = (const float*)d_in[4];
    const float* Whh1 = (const float*)d_in[5];
    const float* b1   = (const float*)d_in[6];
    const float* Wsh  = (const float*)d_in[7];
    const float* bsh  = (const float*)d_in[8];
    const float* Wdir = (const float*)d_in[9];
    const float* bdir = (const float*)d_in[10];
    const float* Wmag = (const float*)d_in[11];
    const float* bmag = (const float*)d_in[12];
    float* out = (float*)d_out;

    cudaFuncSetAttribute(lstm_step_kernel,
                         cudaFuncAttributeMaxDynamicSharedMemorySize, STEP_SMEM_BYTES);

    const dim3 gGemm(M_ALL / 128, FOURH / 64);   // (512, 32)
    const int zBlocks = (B_ * H_ + 255) / 256;
    const int cBlocks = (FOURH * H_ / 4 + 255) / 256;

    // layer 0
    zero_state_kernel<<<zBlocks, 256>>>();
    conv_w_kernel<<<cBlocks, 256>>>(Whh0);
    gemm_xw_kernel<<<gGemm, 256>>>(x, 0, Wih0, b0, D_);
    for (int t = 0; t < T_; t++)
        lstm_step_kernel<<<GRID_S, THR_S, STEP_SMEM_BYTES>>>(t, 0);

    // layer 1
    zero_state_kernel<<<zBlocks, 256>>>();
    conv_w_kernel<<<cBlocks, 256>>>(Whh1);
    gemm_xw_kernel<<<gGemm, 256>>>(nullptr, 1, Wih1, b1, H_);
    for (int t = 0; t < T_; t++)
        lstm_step_kernel<<<GRID_S, THR_S, STEP_SMEM_BYTES>>>(t, 1);

    // heads
    head1_kernel<<<B_, 256>>>(Wsh, bsh);
    head2_kernel<<<1, 256>>>(Wdir, bdir, Wmag, bmag, out);
}